// round 6
// baseline (speedup 1.0000x reference)
#include <cuda_runtime.h>
#include <cuda_fp16.h>

#define NN   50000
#define EE   800000
#define DD   128
#define OUTD 64

// ---------------- device scratch (no allocations allowed) ----------------
__device__ __align__(16) float  g_t [NN * DD];   // GEMM output (fp32) / gather source
__device__ __align__(16) __half g_h1[NN * DD];   // layer-1 activations (fp16)
__device__ __align__(16) __half g_h2[NN * DD];   // layer-2 activations (fp16)
__device__ float g_out_norm[NN];
__device__ float g_in_norm [NN];
__device__ int   g_deg_in [NN];
__device__ int   g_deg_out[NN];
__device__ int   g_row_start[NN];
__device__ int   g_cnt[NN];
__device__ int   g_col[EE];
__device__ unsigned long long g_state[64];       // lookback scan state: flag<<32 | value
__device__ __align__(16) float g_Wcat[DD * DD];  // [W3 | skip_W], 128x128

// ---------------- fused zero + Wcat build ----------------
__global__ void k_zero_wcat(const float* __restrict__ W3, const float* __restrict__ skipW) {
    int i = blockIdx.x * blockDim.x + threadIdx.x;
    if (i < NN) { g_deg_in[i] = 0; g_deg_out[i] = 0; g_cnt[i] = 0; }
    if (i < 64) g_state[i] = 0ULL;
    if (i < DD * DD) {
        int k = i >> 7, n = i & 127;
        g_Wcat[i] = (n < OUTD) ? W3[k * OUTD + n] : skipW[k * OUTD + (n - OUTD)];
    }
}

__global__ void k_deg(const int* __restrict__ src, const int* __restrict__ dst) {
    int e = blockIdx.x * blockDim.x + threadIdx.x;
    if (e < EE) {
        atomicAdd(&g_deg_out[src[e]], 1);
        atomicAdd(&g_deg_in [dst[e]], 1);
    }
}

// ---------------- single-pass scan (decoupled lookback) + norms ----------------
// grid = 49 blocks x 1024 (all resident on 148 SMs -> spin is deadlock-free)
__global__ void __launch_bounds__(1024) k_scan_norms() {
    __shared__ int warp_sums[32];
    __shared__ int s_prefix;
    int bid = blockIdx.x, tid = threadIdx.x;
    int lane = tid & 31, wid = tid >> 5;
    int i = bid * 1024 + tid;
    int v = (i < NN) ? g_deg_in[i] : 0;

    // warp inclusive scan
    int x = v;
    #pragma unroll
    for (int off = 1; off < 32; off <<= 1) {
        int t = __shfl_up_sync(0xffffffffu, x, off);
        if (lane >= off) x += t;
    }
    if (lane == 31) warp_sums[wid] = x;
    __syncthreads();
    if (wid == 0) {
        int w = warp_sums[lane];
        #pragma unroll
        for (int off = 1; off < 32; off <<= 1) {
            int t = __shfl_up_sync(0xffffffffu, w, off);
            if (lane >= off) w += t;
        }
        warp_sums[lane] = w;   // inclusive scan of warp sums
    }
    __syncthreads();
    int wexcl = (wid == 0) ? 0 : warp_sums[wid - 1];
    int incl  = wexcl + x;                 // inclusive within block
    int btotal = warp_sums[31];

    if (tid == 0) {
        if (bid == 0) {
            s_prefix = 0;
            atomicExch(&g_state[0], (2ULL << 32) | (unsigned)btotal);
        } else {
            atomicExch(&g_state[bid], (1ULL << 32) | (unsigned)btotal);
            int p = 0;
            for (int j = bid - 1; j >= 0; --j) {
                unsigned long long s;
                do { s = atomicAdd(&g_state[j], 0ULL); } while ((s >> 32) == 0ULL);
                p += (int)(unsigned)s;
                if ((s >> 32) == 2ULL) break;
            }
            s_prefix = p;
            atomicExch(&g_state[bid], (2ULL << 32) | (unsigned)(p + btotal));
        }
    }
    __syncthreads();

    if (i < NN) {
        g_row_start[i] = s_prefix + incl - v;      // global exclusive prefix
        int od = g_deg_out[i];
        g_out_norm[i] = rsqrtf((float)(od > 1 ? od : 1));
        g_in_norm [i] = rsqrtf((float)(v  > 1 ? v  : 1));
    }
}

__global__ void k_fill(const int* __restrict__ src, const int* __restrict__ dst) {
    int e = blockIdx.x * blockDim.x + threadIdx.x;
    if (e < EE) {
        int d = dst[e];
        int p = g_row_start[d] + atomicAdd(&g_cnt[d], 1);
        g_col[p] = src[e];
    }
}

// ---------------- tensor-core GEMM: C[N x 128] = A @ B, fp16 mma, fp32 accum ----
// layer 0: A = node_feats (fp32 ext), B = W1 (ext),  scaleCols = 128
// layer 1: A = g_h1 (fp16),           B = W2 (ext),  scaleCols = 128
// layer 2: A = g_h2 (fp16),           B = g_Wcat,    scaleCols = 64
__global__ void __launch_bounds__(256) k_gemm(const float* __restrict__ extA,
                                              const float* __restrict__ extB,
                                              int layer, int scaleCols) {
    const float* B = (layer == 2) ? g_Wcat : extB;

    __shared__ __half As[128][88];    // +24 pad: 176B stride (16B-aligned, ldmatrix conflict-free)
    __shared__ __half Bs[64][136];    // +8 pad: 272B stride

    int tid  = threadIdx.x;
    int lane = tid & 31;
    int wid  = tid >> 5;
    int row0 = blockIdx.x * 128;
    int mbase = (wid & 1) * 64;
    int nbase = (wid >> 1) * 32;

    float acc[4][4][4];
    #pragma unroll
    for (int mt = 0; mt < 4; mt++)
        #pragma unroll
        for (int nt = 0; nt < 4; nt++)
            #pragma unroll
            for (int q = 0; q < 4; q++) acc[mt][nt][q] = 0.f;

    for (int kb = 0; kb < 128; kb += 64) {
        // ---- stage A ----
        if (layer == 0) {
            #pragma unroll
            for (int it = 0; it < 8; ++it) {
                int idx = tid + it * 256;       // 128 rows x 16 float4
                int r   = idx >> 4;
                int c4  = idx & 15;
                int gr  = row0 + r;
                float4 v = (gr < NN) ? *(const float4*)&extA[gr * 128 + kb + c4 * 4]
                                     : make_float4(0.f, 0.f, 0.f, 0.f);
                __half2* dh = (__half2*)&As[r][c4 * 4];
                dh[0] = __floats2half2_rn(v.x, v.y);
                dh[1] = __floats2half2_rn(v.z, v.w);
            }
        } else {
            const __half* Ah = (layer == 1) ? g_h1 : g_h2;
            #pragma unroll
            for (int it = 0; it < 4; ++it) {
                int idx = tid + it * 256;       // 128 rows x 8 uint4 (8 halves each)
                int r   = idx >> 3;
                int c8  = idx & 7;
                int gr  = row0 + r;
                uint4 v = make_uint4(0u, 0u, 0u, 0u);
                if (gr < NN) v = *(const uint4*)&Ah[gr * 128 + kb + c8 * 8];
                *(uint4*)&As[r][c8 * 8] = v;
            }
        }
        // ---- stage B (fp32 -> fp16) ----
        #pragma unroll
        for (int it = 0; it < 8; ++it) {
            int idx = tid + it * 256;           // 64 k x 32 float4
            int k   = idx >> 5;
            int c4  = idx & 31;
            float4 v = *(const float4*)&B[(kb + k) * 128 + c4 * 4];
            __half2* dh = (__half2*)&Bs[k][c4 * 4];
            dh[0] = __floats2half2_rn(v.x, v.y);
            dh[1] = __floats2half2_rn(v.z, v.w);
        }
        __syncthreads();

        #pragma unroll
        for (int ks = 0; ks < 4; ++ks) {        // 4 x k16
            unsigned a[4][4], b[4][2];
            int arow  = mbase + (lane & 15);
            int akofs = ks * 16 + (lane >> 4) * 8;
            #pragma unroll
            for (int mt = 0; mt < 4; ++mt) {
                unsigned ad = (unsigned)__cvta_generic_to_shared(&As[arow + mt * 16][akofs]);
                asm volatile("ldmatrix.sync.aligned.m8n8.x4.shared.b16 {%0,%1,%2,%3}, [%4];"
                    : "=r"(a[mt][0]), "=r"(a[mt][1]), "=r"(a[mt][2]), "=r"(a[mt][3]) : "r"(ad));
            }
            int bk = ks * 16 + ((lane >> 3) & 1) * 8 + (lane & 7);
            #pragma unroll
            for (int np = 0; np < 2; ++np) {
                int bn = nbase + np * 16 + (lane >> 4) * 8;
                unsigned ad = (unsigned)__cvta_generic_to_shared(&Bs[bk][bn]);
                unsigned r0, r1, r2, r3;
                asm volatile("ldmatrix.sync.aligned.m8n8.x4.trans.shared.b16 {%0,%1,%2,%3}, [%4];"
                    : "=r"(r0), "=r"(r1), "=r"(r2), "=r"(r3) : "r"(ad));
                b[np * 2][0] = r0; b[np * 2][1] = r1;
                b[np * 2 + 1][0] = r2; b[np * 2 + 1][1] = r3;
            }
            #pragma unroll
            for (int mt = 0; mt < 4; ++mt)
                #pragma unroll
                for (int nt = 0; nt < 4; ++nt)
                    asm volatile("mma.sync.aligned.m16n8k16.row.col.f32.f16.f16.f32 "
                        "{%0,%1,%2,%3}, {%4,%5,%6,%7}, {%8,%9}, {%0,%1,%2,%3};"
                        : "+f"(acc[mt][nt][0]), "+f"(acc[mt][nt][1]),
                          "+f"(acc[mt][nt][2]), "+f"(acc[mt][nt][3])
                        : "r"(a[mt][0]), "r"(a[mt][1]), "r"(a[mt][2]), "r"(a[mt][3]),
                          "r"(b[nt][0]), "r"(b[nt][1]));
        }
        __syncthreads();
    }

    // epilogue: out_norm scaling on cols < scaleCols, fp32 float2 stores
    #pragma unroll
    for (int mt = 0; mt < 4; ++mt) {
        int r0g = row0 + mbase + mt * 16 + (lane >> 2);
        int r1g = r0g + 8;
        float s0 = (r0g < NN) ? g_out_norm[r0g] : 0.f;
        float s1 = (r1g < NN) ? g_out_norm[r1g] : 0.f;
        #pragma unroll
        for (int nt = 0; nt < 4; ++nt) {
            int c = nbase + nt * 8 + (lane & 3) * 2;
            float m0 = (c < scaleCols) ? s0 : 1.f;
            float m1 = (c < scaleCols) ? s1 : 1.f;
            if (r0g < NN)
                *(float2*)&g_t[r0g * 128 + c] = make_float2(acc[mt][nt][0] * m0, acc[mt][nt][1] * m0);
            if (r1g < NN)
                *(float2*)&g_t[r1g * 128 + c] = make_float2(acc[mt][nt][2] * m1, acc[mt][nt][3] * m1);
        }
    }
}

// ---------------- aggregation: CSR gather (MLP 8, shfl indices) + epilogues ----
// EPI 1: h1 = relu(in_norm*acc + b1)              -> g_h1 (fp16)
// EPI 2: h2 = relu(0.6*h1 + 0.4*(in_norm*acc+b2)) -> g_h2 (fp16)
// EPI 3: out = 0.6*(skip+skip_b) + 0.4*(in_norm*acc+b3) -> extOut (fp32, D=64)
template <int EPI>
__global__ void __launch_bounds__(256) k_agg(const float* __restrict__ bmain,
                                             const float* __restrict__ baux,
                                             float* __restrict__ extOut) {
    const float4* X = (const float4*)g_t;        // row stride = 32 float4

    if (EPI != 3) {
        int node = blockIdx.x * 8 + (threadIdx.x >> 5);
        int g    = threadIdx.x & 31;
        if (node >= NN) return;
        int e0  = g_row_start[node];
        int deg = g_deg_in[node];

        float4 acc = make_float4(0.f, 0.f, 0.f, 0.f);
        for (int base = 0; base < deg; base += 32) {
            int m = deg - base; if (m > 32) m = 32;
            int idx = (g < m) ? g_col[e0 + base + g] : 0;
            int j = 0;
            for (; j + 8 <= m; j += 8) {
                int s[8];
                #pragma unroll
                for (int q = 0; q < 8; ++q) s[q] = __shfl_sync(0xffffffffu, idx, j + q);
                float4 v[8];
                #pragma unroll
                for (int q = 0; q < 8; ++q) v[q] = X[s[q] * 32 + g];
                acc.x += ((v[0].x + v[1].x) + (v[2].x + v[3].x)) + ((v[4].x + v[5].x) + (v[6].x + v[7].x));
                acc.y += ((v[0].y + v[1].y) + (v[2].y + v[3].y)) + ((v[4].y + v[5].y) + (v[6].y + v[7].y));
                acc.z += ((v[0].z + v[1].z) + (v[2].z + v[3].z)) + ((v[4].z + v[5].z) + (v[6].z + v[7].z));
                acc.w += ((v[0].w + v[1].w) + (v[2].w + v[3].w)) + ((v[4].w + v[5].w) + (v[6].w + v[7].w));
            }
            for (; j + 4 <= m; j += 4) {
                int s[4];
                #pragma unroll
                for (int q = 0; q < 4; ++q) s[q] = __shfl_sync(0xffffffffu, idx, j + q);
                float4 v[4];
                #pragma unroll
                for (int q = 0; q < 4; ++q) v[q] = X[s[q] * 32 + g];
                acc.x += (v[0].x + v[1].x) + (v[2].x + v[3].x);
                acc.y += (v[0].y + v[1].y) + (v[2].y + v[3].y);
                acc.z += (v[0].z + v[1].z) + (v[2].z + v[3].z);
                acc.w += (v[0].w + v[1].w) + (v[2].w + v[3].w);
            }
            for (; j < m; ++j) {
                int s = __shfl_sync(0xffffffffu, idx, j);
                float4 v = X[s * 32 + g];
                acc.x += v.x; acc.y += v.y; acc.z += v.z; acc.w += v.w;
            }
        }

        float w = g_in_norm[node];
        float4 b = ((const float4*)bmain)[g];
        if (EPI == 1) {
            float rx = fmaxf(acc.x * w + b.x, 0.f);
            float ry = fmaxf(acc.y * w + b.y, 0.f);
            float rz = fmaxf(acc.z * w + b.z, 0.f);
            float rw = fmaxf(acc.w * w + b.w, 0.f);
            __half2 h0 = __floats2half2_rn(rx, ry);
            __half2 h1 = __floats2half2_rn(rz, rw);
            uint2 u; u.x = *(unsigned*)&h0; u.y = *(unsigned*)&h1;
            ((uint2*)g_h1)[node * 32 + g] = u;
        } else {
            uint2 up = ((const uint2*)g_h1)[node * 32 + g];
            float2 p0 = __half22float2(*(__half2*)&up.x);
            float2 p1 = __half22float2(*(__half2*)&up.y);
            float rx = fmaxf(0.6f * p0.x + 0.4f * (acc.x * w + b.x), 0.f);
            float ry = fmaxf(0.6f * p0.y + 0.4f * (acc.y * w + b.y), 0.f);
            float rz = fmaxf(0.6f * p1.x + 0.4f * (acc.z * w + b.z), 0.f);
            float rw = fmaxf(0.6f * p1.y + 0.4f * (acc.w * w + b.w), 0.f);
            __half2 h0 = __floats2half2_rn(rx, ry);
            __half2 h1 = __floats2half2_rn(rz, rw);
            uint2 u; u.x = *(unsigned*)&h0; u.y = *(unsigned*)&h1;
            ((uint2*)g_h2)[node * 32 + g] = u;
        }
    } else {
        // D=64: 16 lanes per node, 2 nodes per warp
        int node = blockIdx.x * 16 + (threadIdx.x >> 4);
        int g    = threadIdx.x & 15;
        if (node >= NN) return;
        int e0  = g_row_start[node];
        int deg = g_deg_in[node];

        float4 acc = make_float4(0.f, 0.f, 0.f, 0.f);
        for (int base = 0; base < deg; base += 16) {
            int m = deg - base; if (m > 16) m = 16;
            int idx = (g < m) ? g_col[e0 + base + g] : 0;
            int j = 0;
            for (; j + 8 <= m; j += 8) {
                int s[8];
                #pragma unroll
                for (int q = 0; q < 8; ++q) s[q] = __shfl_sync(0xffffffffu, idx, j + q, 16);
                float4 v[8];
                #pragma unroll
                for (int q = 0; q < 8; ++q) v[q] = X[s[q] * 32 + g];
                acc.x += ((v[0].x + v[1].x) + (v[2].x + v[3].x)) + ((v[4].x + v[5].x) + (v[6].x + v[7].x));
                acc.y += ((v[0].y + v[1].y) + (v[2].y + v[3].y)) + ((v[4].y + v[5].y) + (v[6].y + v[7].y));
                acc.z += ((v[0].z + v[1].z) + (v[2].z + v[3].z)) + ((v[4].z + v[5].z) + (v[6].z + v[7].z));
                acc.w += ((v[0].w + v[1].w) + (v[2].w + v[3].w)) + ((v[4].w + v[5].w) + (v[6].w + v[7].w));
            }
            for (; j < m; ++j) {
                int s = __shfl_sync(0xffffffffu, idx, j, 16);
                float4 v = X[s * 32 + g];
                acc.x += v.x; acc.y += v.y; acc.z += v.z; acc.w += v.w;
            }
        }

        float w = g_in_norm[node];
        float4 b  = ((const float4*)bmain)[g];
        float4 sb = ((const float4*)baux)[g];
        float4 s4 = X[node * 32 + 16 + g];   // skip half (unscaled)
        float4 r;
        r.x = 0.6f * (s4.x + sb.x) + 0.4f * (acc.x * w + b.x);
        r.y = 0.6f * (s4.y + sb.y) + 0.4f * (acc.y * w + b.y);
        r.z = 0.6f * (s4.z + sb.z) + 0.4f * (acc.z * w + b.z);
        r.w = 0.6f * (s4.w + sb.w) + 0.4f * (acc.w * w + b.w);
        ((float4*)extOut)[node * 16 + g] = r;
    }
}

// ---------------- host launcher ----------------
extern "C" void kernel_launch(void* const* d_in, const int* in_sizes, int n_in,
                              void* d_out, int out_size) {
    const float* node_feats = (const float*)d_in[0];
    const int*   edge_index = (const int*)d_in[1];
    const float* W1    = (const float*)d_in[2];
    const float* b1    = (const float*)d_in[3];
    const float* W2    = (const float*)d_in[4];
    const float* b2    = (const float*)d_in[5];
    const float* W3    = (const float*)d_in[6];
    const float* b3    = (const float*)d_in[7];
    const float* skipW = (const float*)d_in[8];
    const float* skipb = (const float*)d_in[9];
    float* out = (float*)d_out;

    const int* src = edge_index;
    const int* dst = edge_index + EE;

    const int TB = 256;
    int nb_nodes = (NN + TB - 1) / TB;       // 196 (also covers 128*128 Wcat)
    int nb_edges = (EE + TB - 1) / TB;       // 3125
    int nb_scan  = (NN + 1023) / 1024;       // 49
    int nb_gemm  = (NN + 127) / 128;         // 391

    k_zero_wcat <<<nb_nodes, TB>>>(W3, skipW);
    k_deg       <<<nb_edges, TB>>>(src, dst);
    k_scan_norms<<<nb_scan, 1024>>>();
    k_fill      <<<nb_edges, TB>>>(src, dst);

    // layer 1
    k_gemm  <<<nb_gemm, 256>>>(node_feats, W1, 0, 128);
    k_agg<1><<<(NN + 7) / 8, 256>>>(b1, nullptr, nullptr);
    // layer 2
    k_gemm  <<<nb_gemm, 256>>>(nullptr, W2, 1, 128);
    k_agg<2><<<(NN + 7) / 8, 256>>>(b2, nullptr, nullptr);
    // layer 3 (fused [W3|skip_W] GEMM; only W3 half out_norm-scaled)
    k_gemm  <<<nb_gemm, 256>>>(nullptr, nullptr, 2, 64);
    k_agg<3><<<(NN + 15) / 16, 256>>>(b3, skipb, out);
}

// round 7
// speedup vs baseline: 1.2200x; 1.2200x over previous
#include <cuda_runtime.h>
#include <cuda_fp16.h>

#define NN   50000
#define EE   800000
#define DD   128
#define OUTD 64

// ---------------- device scratch (no allocations allowed) ----------------
__device__ __align__(16) float  g_t  [NN * DD];  // GEMM output (fp32) / gather source
__device__ __align__(16) __half g_x16[NN * DD];  // node_feats in fp16
__device__ __align__(16) __half g_h1 [NN * DD];  // layer-1 activations (fp16)
__device__ __align__(16) __half g_h2 [NN * DD];  // layer-2 activations (fp16)
__device__ float g_out_norm[NN];
__device__ float g_in_norm [NN];
__device__ int   g_deg_in [NN];
__device__ int   g_deg_out[NN];
__device__ int   g_row_start[NN];
__device__ int   g_cnt[NN];
__device__ int   g_col[EE];
__device__ int   g_bsum[64];
__device__ __align__(16) __half g_w1h  [DD * DD];  // W1 fp16
__device__ __align__(16) __half g_w2h  [DD * DD];  // W2 fp16
__device__ __align__(16) __half g_wcat [DD * DD];  // [W3 | skip_W] fp16

// ---------------- setup: zero counters + fp16 weight prep ----------------
__global__ void k_zero_w16(const float* __restrict__ W1, const float* __restrict__ W2,
                           const float* __restrict__ W3, const float* __restrict__ skipW) {
    int i = blockIdx.x * blockDim.x + threadIdx.x;
    if (i < NN) { g_deg_in[i] = 0; g_deg_out[i] = 0; g_cnt[i] = 0; }
    if (i < DD * DD) {
        int k = i >> 7, n = i & 127;
        g_w1h[i]  = __float2half_rn(W1[i]);
        g_w2h[i]  = __float2half_rn(W2[i]);
        g_wcat[i] = __float2half_rn((n < OUTD) ? W3[k * OUTD + n]
                                               : skipW[k * OUTD + (n - OUTD)]);
    }
}

// ---------------- degrees + node_feats fp16 conversion (fused, same shape) ----
__global__ void k_deg_x16(const int* __restrict__ src, const int* __restrict__ dst,
                          const float* __restrict__ x) {
    int e = blockIdx.x * blockDim.x + threadIdx.x;
    if (e < EE) {
        atomicAdd(&g_deg_out[src[e]], 1);
        atomicAdd(&g_deg_in [dst[e]], 1);
        // convert 8 elems of node_feats (EE threads * 8 = NN*DD exactly)
        int base = e * 8;
        float4 v0 = *(const float4*)&x[base];
        float4 v1 = *(const float4*)&x[base + 4];
        union { uint4 u; __half2 h[4]; } pk;
        pk.h[0] = __floats2half2_rn(v0.x, v0.y);
        pk.h[1] = __floats2half2_rn(v0.z, v0.w);
        pk.h[2] = __floats2half2_rn(v1.x, v1.y);
        pk.h[3] = __floats2half2_rn(v1.z, v1.w);
        *(uint4*)&g_x16[base] = pk.u;
    }
}

// ---------------- 3-phase scan (proven R5 form) + norms in phase 3 ----------
__global__ void k_scan1() {
    __shared__ int sh[1024];
    int i = blockIdx.x * 1024 + threadIdx.x;
    int v = (i < NN) ? g_deg_in[i] : 0;
    sh[threadIdx.x] = v;
    __syncthreads();
    #pragma unroll
    for (int off = 1; off < 1024; off <<= 1) {
        int t = (threadIdx.x >= off) ? sh[threadIdx.x - off] : 0;
        __syncthreads();
        sh[threadIdx.x] += t;
        __syncthreads();
    }
    if (i < NN) g_row_start[i] = sh[threadIdx.x] - v;
    if (threadIdx.x == 1023) g_bsum[blockIdx.x] = sh[1023];
}

__global__ void k_scan2(int nblocks) {
    __shared__ int sh[64];
    int t = threadIdx.x;
    int v = (t < nblocks) ? g_bsum[t] : 0;
    sh[t] = v;
    __syncthreads();
    #pragma unroll
    for (int off = 1; off < 64; off <<= 1) {
        int u = (t >= off) ? sh[t - off] : 0;
        __syncthreads();
        sh[t] += u;
        __syncthreads();
    }
    if (t < nblocks) g_bsum[t] = sh[t] - v;
}

__global__ void k_scan3_norms() {
    int i = blockIdx.x * blockDim.x + threadIdx.x;
    if (i < NN) {
        g_row_start[i] += g_bsum[i >> 10];
        int od = g_deg_out[i], id = g_deg_in[i];
        g_out_norm[i] = rsqrtf((float)(od > 1 ? od : 1));
        g_in_norm [i] = rsqrtf((float)(id > 1 ? id : 1));
    }
}

__global__ void k_fill(const int* __restrict__ src, const int* __restrict__ dst) {
    int e = blockIdx.x * blockDim.x + threadIdx.x;
    if (e < EE) {
        int d = dst[e];
        int p = g_row_start[d] + atomicAdd(&g_cnt[d], 1);
        g_col[p] = src[e];
    }
}

// ---------------- tensor-core GEMM: all-fp16 operands, raw uint4 staging ----
// layer 0: A = g_x16, B = g_w1h,  scaleCols = 128
// layer 1: A = g_h1,  B = g_w2h,  scaleCols = 128
// layer 2: A = g_h2,  B = g_wcat, scaleCols = 64  (skip half unscaled)
__global__ void __launch_bounds__(256) k_gemm(int layer, int scaleCols) {
    const __half* A = (layer == 0) ? g_x16 : (layer == 1) ? g_h1 : g_h2;
    const __half* B = (layer == 0) ? g_w1h : (layer == 1) ? g_w2h : g_wcat;

    __shared__ __half As[128][88];    // +24 pad: 176B stride (16B-aligned)
    __shared__ __half Bs[64][136];    // +8 pad: 272B stride

    int tid  = threadIdx.x;
    int lane = tid & 31;
    int wid  = tid >> 5;
    int row0 = blockIdx.x * 128;
    int mbase = (wid & 1) * 64;
    int nbase = (wid >> 1) * 32;

    float acc[4][4][4];
    #pragma unroll
    for (int mt = 0; mt < 4; mt++)
        #pragma unroll
        for (int nt = 0; nt < 4; nt++)
            #pragma unroll
            for (int q = 0; q < 4; q++) acc[mt][nt][q] = 0.f;

    for (int kb = 0; kb < 128; kb += 64) {
        // stage A: 128 rows x 64 halves, raw 16B copies (4 iters)
        #pragma unroll
        for (int it = 0; it < 4; ++it) {
            int idx = tid + it * 256;           // 128 x 8 uint4
            int r   = idx >> 3;
            int c8  = idx & 7;
            int gr  = row0 + r;
            uint4 v = make_uint4(0u, 0u, 0u, 0u);
            if (gr < NN) v = *(const uint4*)&A[gr * 128 + kb + c8 * 8];
            *(uint4*)&As[r][c8 * 8] = v;
        }
        // stage B: 64 k x 128 halves, raw 16B copies (4 iters)
        #pragma unroll
        for (int it = 0; it < 4; ++it) {
            int idx = tid + it * 256;           // 64 x 16 uint4
            int k   = idx >> 4;
            int c8  = idx & 15;
            uint4 v = *(const uint4*)&B[(kb + k) * 128 + c8 * 8];
            *(uint4*)&Bs[k][c8 * 8] = v;
        }
        __syncthreads();

        #pragma unroll
        for (int ks = 0; ks < 4; ++ks) {        // 4 x k16
            unsigned a[4][4], b[4][2];
            int arow  = mbase + (lane & 15);
            int akofs = ks * 16 + (lane >> 4) * 8;
            #pragma unroll
            for (int mt = 0; mt < 4; ++mt) {
                unsigned ad = (unsigned)__cvta_generic_to_shared(&As[arow + mt * 16][akofs]);
                asm volatile("ldmatrix.sync.aligned.m8n8.x4.shared.b16 {%0,%1,%2,%3}, [%4];"
                    : "=r"(a[mt][0]), "=r"(a[mt][1]), "=r"(a[mt][2]), "=r"(a[mt][3]) : "r"(ad));
            }
            int bk = ks * 16 + ((lane >> 3) & 1) * 8 + (lane & 7);
            #pragma unroll
            for (int np = 0; np < 2; ++np) {
                int bn = nbase + np * 16 + (lane >> 4) * 8;
                unsigned ad = (unsigned)__cvta_generic_to_shared(&Bs[bk][bn]);
                unsigned r0, r1, r2, r3;
                asm volatile("ldmatrix.sync.aligned.m8n8.x4.trans.shared.b16 {%0,%1,%2,%3}, [%4];"
                    : "=r"(r0), "=r"(r1), "=r"(r2), "=r"(r3) : "r"(ad));
                b[np * 2][0] = r0; b[np * 2][1] = r1;
                b[np * 2 + 1][0] = r2; b[np * 2 + 1][1] = r3;
            }
            #pragma unroll
            for (int mt = 0; mt < 4; ++mt)
                #pragma unroll
                for (int nt = 0; nt < 4; ++nt)
                    asm volatile("mma.sync.aligned.m16n8k16.row.col.f32.f16.f16.f32 "
                        "{%0,%1,%2,%3}, {%4,%5,%6,%7}, {%8,%9}, {%0,%1,%2,%3};"
                        : "+f"(acc[mt][nt][0]), "+f"(acc[mt][nt][1]),
                          "+f"(acc[mt][nt][2]), "+f"(acc[mt][nt][3])
                        : "r"(a[mt][0]), "r"(a[mt][1]), "r"(a[mt][2]), "r"(a[mt][3]),
                          "r"(b[nt][0]), "r"(b[nt][1]));
        }
        __syncthreads();
    }

    // epilogue: out_norm scaling on cols < scaleCols, fp32 float2 stores
    #pragma unroll
    for (int mt = 0; mt < 4; ++mt) {
        int r0g = row0 + mbase + mt * 16 + (lane >> 2);
        int r1g = r0g + 8;
        float s0 = (r0g < NN) ? g_out_norm[r0g] : 0.f;
        float s1 = (r1g < NN) ? g_out_norm[r1g] : 0.f;
        #pragma unroll
        for (int nt = 0; nt < 4; ++nt) {
            int c = nbase + nt * 8 + (lane & 3) * 2;
            float m0 = (c < scaleCols) ? s0 : 1.f;
            float m1 = (c < scaleCols) ? s1 : 1.f;
            if (r0g < NN)
                *(float2*)&g_t[r0g * 128 + c] = make_float2(acc[mt][nt][0] * m0, acc[mt][nt][1] * m0);
            if (r1g < NN)
                *(float2*)&g_t[r1g * 128 + c] = make_float2(acc[mt][nt][2] * m1, acc[mt][nt][3] * m1);
        }
    }
}

// ---------------- aggregation (R5 loop: scalar idx loads, MLP 4) + epilogues --
// EPI 1: h1 = relu(in_norm*acc + b1)              -> g_h1 (fp16)
// EPI 2: h2 = relu(0.6*h1 + 0.4*(in_norm*acc+b2)) -> g_h2 (fp16)
// EPI 3: out = 0.6*(skip+skip_b) + 0.4*(in_norm*acc+b3) -> extOut (fp32, D=64)
template <int EPI>
__global__ void __launch_bounds__(256) k_agg(const float* __restrict__ bmain,
                                             const float* __restrict__ baux,
                                             float* __restrict__ extOut) {
    constexpr int G = (EPI == 3) ? 16 : 32;   // lanes per node (float4 each)
    int node = blockIdx.x * (256 / G) + threadIdx.x / G;
    int g    = threadIdx.x & (G - 1);
    if (node >= NN) return;

    int e   = g_row_start[node];
    int end = e + g_deg_in[node];
    const float4* X = (const float4*)g_t;   // row stride = 32 float4

    float4 acc = make_float4(0.f, 0.f, 0.f, 0.f);
    for (; e + 4 <= end; e += 4) {
        int s0 = g_col[e], s1 = g_col[e + 1], s2 = g_col[e + 2], s3 = g_col[e + 3];
        float4 v0 = X[s0 * 32 + g];
        float4 v1 = X[s1 * 32 + g];
        float4 v2 = X[s2 * 32 + g];
        float4 v3 = X[s3 * 32 + g];
        acc.x += (v0.x + v1.x) + (v2.x + v3.x);
        acc.y += (v0.y + v1.y) + (v2.y + v3.y);
        acc.z += (v0.z + v1.z) + (v2.z + v3.z);
        acc.w += (v0.w + v1.w) + (v2.w + v3.w);
    }
    for (; e < end; ++e) {
        int s = g_col[e];
        float4 v = X[s * 32 + g];
        acc.x += v.x; acc.y += v.y; acc.z += v.z; acc.w += v.w;
    }

    float w = g_in_norm[node];
    float4 b = ((const float4*)bmain)[g];
    if (EPI == 1) {
        float rx = fmaxf(acc.x * w + b.x, 0.f);
        float ry = fmaxf(acc.y * w + b.y, 0.f);
        float rz = fmaxf(acc.z * w + b.z, 0.f);
        float rw = fmaxf(acc.w * w + b.w, 0.f);
        __half2 h0 = __floats2half2_rn(rx, ry);
        __half2 h1 = __floats2half2_rn(rz, rw);
        uint2 u; u.x = *(unsigned*)&h0; u.y = *(unsigned*)&h1;
        ((uint2*)g_h1)[node * 32 + g] = u;
    } else if (EPI == 2) {
        uint2 up = ((const uint2*)g_h1)[node * 32 + g];
        float2 p0 = __half22float2(*(__half2*)&up.x);
        float2 p1 = __half22float2(*(__half2*)&up.y);
        float rx = fmaxf(0.6f * p0.x + 0.4f * (acc.x * w + b.x), 0.f);
        float ry = fmaxf(0.6f * p0.y + 0.4f * (acc.y * w + b.y), 0.f);
        float rz = fmaxf(0.6f * p1.x + 0.4f * (acc.z * w + b.z), 0.f);
        float rw = fmaxf(0.6f * p1.y + 0.4f * (acc.w * w + b.w), 0.f);
        __half2 h0 = __floats2half2_rn(rx, ry);
        __half2 h1 = __floats2half2_rn(rz, rw);
        uint2 u; u.x = *(unsigned*)&h0; u.y = *(unsigned*)&h1;
        ((uint2*)g_h2)[node * 32 + g] = u;
    } else {
        float4 sb = ((const float4*)baux)[g];
        float4 s4 = X[node * 32 + 16 + g];   // skip half (unscaled)
        float4 r;
        r.x = 0.6f * (s4.x + sb.x) + 0.4f * (acc.x * w + b.x);
        r.y = 0.6f * (s4.y + sb.y) + 0.4f * (acc.y * w + b.y);
        r.z = 0.6f * (s4.z + sb.z) + 0.4f * (acc.z * w + b.z);
        r.w = 0.6f * (s4.w + sb.w) + 0.4f * (acc.w * w + b.w);
        ((float4*)extOut)[node * 16 + g] = r;
    }
}

// ---------------- host launcher ----------------
extern "C" void kernel_launch(void* const* d_in, const int* in_sizes, int n_in,
                              void* d_out, int out_size) {
    const float* node_feats = (const float*)d_in[0];
    const int*   edge_index = (const int*)d_in[1];
    const float* W1    = (const float*)d_in[2];
    const float* b1    = (const float*)d_in[3];
    const float* W2    = (const float*)d_in[4];
    const float* b2    = (const float*)d_in[5];
    const float* W3    = (const float*)d_in[6];
    const float* b3    = (const float*)d_in[7];
    const float* skipW = (const float*)d_in[8];
    const float* skipb = (const float*)d_in[9];
    float* out = (float*)d_out;

    const int* src = edge_index;
    const int* dst = edge_index + EE;

    const int TB = 256;
    int nb_nodes = (NN + TB - 1) / TB;       // 196
    int nb_edges = (EE + TB - 1) / TB;       // 3125
    int nb_scan  = (NN + 1023) / 1024;       // 49
    int nb_gemm  = (NN + 127) / 128;         // 391

    k_zero_w16   <<<nb_nodes, TB>>>(W1, W2, W3, skipW);
    k_deg_x16    <<<nb_edges, TB>>>(src, dst, node_feats);
    k_scan1      <<<nb_scan, 1024>>>();
    k_scan2      <<<1, 64>>>(nb_scan);
    k_scan3_norms<<<nb_nodes, TB>>>();
    k_fill       <<<nb_edges, TB>>>(src, dst);

    // layer 1
    k_gemm  <<<nb_gemm, 256>>>(0, 128);
    k_agg<1><<<(NN + 7) / 8, 256>>>(b1, nullptr, nullptr);
    // layer 2
    k_gemm  <<<nb_gemm, 256>>>(1, 128);
    k_agg<2><<<(NN + 7) / 8, 256>>>(b2, nullptr, nullptr);
    // layer 3 (fused [W3|skip_W] GEMM; only W3 half out_norm-scaled)
    k_gemm  <<<nb_gemm, 256>>>(2, 64);
    k_agg<3><<<(NN + 15) / 16, 256>>>(b3, skipb, out);
}